// round 4
// baseline (speedup 1.0000x reference)
#include <cuda_runtime.h>
#include <math.h>

#define B_DIM 128
#define S_DIM 512
#define IN_DIM 128
#define D_DIM 64
#define G_DIM 256   // 4*D
#define TILE_R 64

typedef unsigned long long ull;

// ---- packed f32x2 helpers (Blackwell; ptxas never auto-fuses these) ----
__device__ __forceinline__ void ffma2(ull& a, ull x, ull y) {
    asm("fma.rn.f32x2 %0, %1, %2, %0;" : "+l"(a) : "l"(x), "l"(y));
}
__device__ __forceinline__ ull fmaf2(ull a, ull b, ull c) {
    ull d; asm("fma.rn.f32x2 %0, %1, %2, %3;" : "=l"(d) : "l"(a), "l"(b), "l"(c)); return d;
}
__device__ __forceinline__ ull mulf2(ull x, ull y) {
    ull r; asm("mul.rn.f32x2 %0, %1, %2;" : "=l"(r) : "l"(x), "l"(y)); return r;
}
__device__ __forceinline__ ull addf2(ull x, ull y) {
    ull r; asm("add.rn.f32x2 %0, %1, %2;" : "=l"(r) : "l"(x), "l"(y)); return r;
}
__device__ __forceinline__ ull packf2(float lo, float hi) {
    ull r; asm("mov.b64 %0, {%1, %2};" : "=l"(r) : "f"(lo), "f"(hi)); return r;
}
__device__ __forceinline__ float2 unpackf2(ull v) {
    float2 f; asm("mov.b64 {%0, %1}, %2;" : "=f"(f.x), "=f"(f.y) : "l"(v)); return f;
}

// Scratch (sanctioned __device__ globals)
__device__ float g_xs[(size_t)S_DIM * B_DIM * G_DIM];   // [s][b][4D]
__device__ float g_Wc[IN_DIM * G_DIM];                  // W_in @ W_s
__device__ float g_bc[G_DIM];                           // b_in @ W_s + b_s

// ---------------------------------------------------------------------------
// Kernel 1: fold input projection into sLSTM input weights.
// ---------------------------------------------------------------------------
__global__ void combine_weights(const float* __restrict__ W_in,
                                const float* __restrict__ b_in,
                                const float* __restrict__ W_s,
                                const float* __restrict__ b_s) {
    int j = threadIdx.x;
    int d = blockIdx.x;
    if (d < IN_DIM) {
        float acc = 0.f;
#pragma unroll
        for (int e = 0; e < D_DIM; e++)
            acc += W_in[d * D_DIM + e] * W_s[e * G_DIM + j];
        g_Wc[d * G_DIM + j] = acc;
    } else {
        float acc = b_s[j];
#pragma unroll
        for (int e = 0; e < D_DIM; e++)
            acc += b_in[e] * W_s[e * G_DIM + j];
        g_bc[j] = acc;
    }
}

// ---------------------------------------------------------------------------
// Kernel 2: xs[s][b][j] = x[b][s][:] @ W_comb[:,j] + b_comb[j]  (packed f32x2)
// ---------------------------------------------------------------------------
__global__ __launch_bounds__(256) void xs_gemm(const float* __restrict__ x) {
    __shared__ __align__(16) float xsm[TILE_R][IN_DIM];
    int t = threadIdx.x;
    int row0 = blockIdx.x * TILE_R;

    const float4* xg = reinterpret_cast<const float4*>(x + (size_t)row0 * IN_DIM);
    float4* xs4 = reinterpret_cast<float4*>(&xsm[0][0]);
#pragma unroll
    for (int i = 0; i < (TILE_R * IN_DIM / 4) / 256; i++)
        xs4[t + i * 256] = xg[t + i * 256];

    ull w2[64];
#pragma unroll
    for (int i = 0; i < 64; i++)
        w2[i] = packf2(g_Wc[(2 * i) * G_DIM + t], g_Wc[(2 * i + 1) * G_DIM + t]);
    float bc = g_bc[t];
    __syncthreads();

    for (int r = 0; r < TILE_R; r += 4) {
        ull a0 = 0, a1 = 0, a2 = 0, a3 = 0;
        const ulonglong2* p0 = reinterpret_cast<const ulonglong2*>(xsm[r + 0]);
        const ulonglong2* p1 = reinterpret_cast<const ulonglong2*>(xsm[r + 1]);
        const ulonglong2* p2 = reinterpret_cast<const ulonglong2*>(xsm[r + 2]);
        const ulonglong2* p3 = reinterpret_cast<const ulonglong2*>(xsm[r + 3]);
#pragma unroll
        for (int dq = 0; dq < 32; dq++) {
            ulonglong2 v0 = p0[dq]; ffma2(a0, v0.x, w2[2*dq]); ffma2(a0, v0.y, w2[2*dq+1]);
            ulonglong2 v1 = p1[dq]; ffma2(a1, v1.x, w2[2*dq]); ffma2(a1, v1.y, w2[2*dq+1]);
            ulonglong2 v2 = p2[dq]; ffma2(a2, v2.x, w2[2*dq]); ffma2(a2, v2.y, w2[2*dq+1]);
            ulonglong2 v3 = p3[dq]; ffma2(a3, v3.x, w2[2*dq]); ffma2(a3, v3.y, w2[2*dq+1]);
        }
#pragma unroll
        for (int rr = 0; rr < 4; rr++) {
            ull av = (rr == 0) ? a0 : (rr == 1) ? a1 : (rr == 2) ? a2 : a3;
            float2 f = unpackf2(av);
            int row = row0 + r + rr;
            int bb = row >> 9;
            int ss = row & 511;
            g_xs[((size_t)ss * B_DIM + bb) * G_DIM + t] = f.x + f.y + bc;
        }
    }
}

// ---------------------------------------------------------------------------
// Kernel 3: persistent recurrence, 1 CTA/batch, 256 threads.
// ONE __syncthreads per step: every warp computes the sLSTM/LN/gate phase (B)
// redundantly into warp-private buffers; cross-warp data (gact, k/v) is
// double-buffered; software pipeline B(i-1) -> A(i) -> C(i-1) -> D(i-2).
// ---------------------------------------------------------------------------
__global__ __launch_bounds__(256, 1) void recur(
    const float* __restrict__ R_s,
    const float* __restrict__ ln_g, const float* __restrict__ ln_b,
    const float* __restrict__ Wq, const float* __restrict__ Wk,
    const float* __restrict__ Wv,
    const float* __restrict__ wi, const float* __restrict__ bi_p,
    const float* __restrict__ wf, const float* __restrict__ bf_p,
    const float* __restrict__ Wo, const float* __restrict__ bo,
    const float* __restrict__ W_fuse, const float* __restrict__ b_fuse,
    float* __restrict__ out)
{
    __shared__ __align__(16) float hs_all[8][64];    // per-warp hs copy
    __shared__ __align__(16) float hso_all[8][64];   // per-warp hso copy
    __shared__ __align__(16) float gact2[2][256];    // double-buffered gates
    __shared__ __align__(16) float kbuf[2][64], vbuf[2][64];
    __shared__ __align__(16) float nm[64];
    __shared__ __align__(16) float qsm[64], omsm[64], numsm[64], hmsm[64];
    __shared__ float red2[2];
    __shared__ float gpart[4][64];

    int t = threadIdx.x;
    int b = blockIdx.x;
    int lane = t & 31;
    int w = t >> 5;
    float* hsw  = hs_all[w];
    float* hsow = hso_all[w];

    // recurrent weight column t, packed (pair i covers rows 2i,2i+1)
    ull R2[32];
#pragma unroll
    for (int i = 0; i < 32; i++)
        R2[i] = packf2(R_s[(2 * i) * G_DIM + t], R_s[(2 * i + 1) * G_DIM + t]);

    ull W2[32];
    if (t < 128) {
        const float* Wsel = (t < 64) ? Wk : Wv;
        int c = t & 63;
#pragma unroll
        for (int i = 0; i < 32; i++)
            W2[i] = packf2(Wsel[(2 * i) * 64 + c], Wsel[(2 * i + 1) * 64 + c]);
    }

    // per-lane B constants (every warp; lane covers dims d0=lane, d1=lane+32)
    const int d0 = lane, d1 = lane + 32;
    float g0 = ln_g[d0], g1 = ln_g[d1], lb0 = ln_b[d0], lb1 = ln_b[d1];
    float wi0 = wi[d0], wi1 = wi[d1], wf0 = wf[d0], wf1 = wf[d1];
    float gwi0 = g0 * wi0, gwi1 = g1 * wi1, gwf0 = g0 * wf0, gwf1 = g1 * wf1;
    float Sgwi, Sgwf, Sbwi, Sbwf;
    {
        float sa = gwi0 + gwi1, sb = gwf0 + gwf1;
        float sc = lb0 * wi0 + lb1 * wi1, sd = lb0 * wf0 + lb1 * wf1;
#pragma unroll
        for (int off = 16; off > 0; off >>= 1) {
            sa += __shfl_xor_sync(0xffffffffu, sa, off);
            sb += __shfl_xor_sync(0xffffffffu, sb, off);
            sc += __shfl_xor_sync(0xffffffffu, sc, off);
            sd += __shfl_xor_sync(0xffffffffu, sd, off);
        }
        Sgwi = sa; Sgwf = sb; Sbwi = sc; Sbwf = sd;
    }
    float cs0 = 0.f, cs1 = 0.f, ns0 = 1.f, ns1 = 1.f;
    if (t < 64) nm[t] = 0.f;
    float bi = bi_p[0];
    float bf = bf_p[0];

    ull C2[8];
#pragma unroll
    for (int i = 0; i < 8; i++) C2[i] = 0ull;

    const int ci = t >> 2;           // C_m row owned
    const int jb = (t & 3) << 4;     // 16-column slice

    const float* xsp = g_xs + (size_t)b * G_DIM + t;
    float gnext = xsp[0];

    // ---- peel i = 0: A(0) with hs = 0 (g = xs only) ----
    {
        float gv = gnext;
        gnext = xsp[(size_t)1 * (B_DIM * G_DIM)];
        float act;
        if (t < 64)       { float e = __expf(2.f * gv); act = 1.f - __fdividef(2.f, e + 1.f); }
        else if (t < 128) { act = __expf(gv); }
        else              { float e = __expf(-gv); act = __fdividef(1.f, 1.f + e); }
        gact2[0][t] = act;
    }
    float im_prev = 0.f, fm_prev = 0.f;
    __syncthreads();

    for (int i = 1; i < S_DIM; i++) {
        // ---- B(i-1) part1: state update (all warps, redundant) ----
        const float* gA = gact2[(i - 1) & 1];
        float z0 = gA[d0], i0v = gA[64 + d0], f0 = gA[128 + d0], o0 = gA[192 + d0];
        float z1 = gA[d1], i1v = gA[64 + d1], f1 = gA[128 + d1], o1 = gA[192 + d1];
        cs0 = f0 * cs0 + i0v * z0; ns0 = f0 * ns0 + i0v;
        cs1 = f1 * cs1 + i1v * z1; ns1 = f1 * ns1 + i1v;
        float h0 = __fdividef(o0 * cs0, ns0);
        float h1 = __fdividef(o1 * cs1, ns1);
        hsw[d0] = h0; hsw[d1] = h1;
        __syncwarp();

        // ---- A(i): g = xs(i) + hs(i-1) @ R_s ; activation ----
        float gv = gnext;
        {
            int sn = (i + 1 < S_DIM) ? (i + 1) : (S_DIM - 1);
            gnext = xsp[(size_t)sn * (B_DIM * G_DIM)];
        }
        {
            ull a0 = 0, a1 = 0, a2 = 0, a3 = 0;
            const ulonglong2* h2 = reinterpret_cast<const ulonglong2*>(hsw);
#pragma unroll
            for (int q = 0; q < 8; q++) {
                ulonglong2 u = h2[2 * q];
                ulonglong2 v = h2[2 * q + 1];
                ffma2(a0, u.x, R2[4 * q]);
                ffma2(a1, u.y, R2[4 * q + 1]);
                ffma2(a2, v.x, R2[4 * q + 2]);
                ffma2(a3, v.y, R2[4 * q + 3]);
            }
            a0 = addf2(a0, a1); a2 = addf2(a2, a3); a0 = addf2(a0, a2);
            float2 p = unpackf2(a0);
            gv += p.x + p.y;
        }
        {
            float act;
            if (t < 64)       { float e = __expf(2.f * gv); act = 1.f - __fdividef(2.f, e + 1.f); }
            else if (t < 128) { act = __expf(gv); }
            else              { float e = __expf(-gv); act = __fdividef(1.f, 1.f + e); }
            gact2[i & 1][t] = act;
        }

        // ---- B(i-1) part2: LN + scalar gates (all warps, redundant) ----
        float im_cur, fm_cur;
        {
            float r1 = h0 + h1;
            float r2 = h0 * h0 + h1 * h1;
            float r3 = h0 * gwi0 + h1 * gwi1;
            float r4 = h0 * gwf0 + h1 * gwf1;
#pragma unroll
            for (int off = 16; off > 0; off >>= 1) {
                r1 += __shfl_xor_sync(0xffffffffu, r1, off);
                r2 += __shfl_xor_sync(0xffffffffu, r2, off);
                r3 += __shfl_xor_sync(0xffffffffu, r3, off);
                r4 += __shfl_xor_sync(0xffffffffu, r4, off);
            }
            float mu  = r1 * 0.015625f;
            float inv = rsqrtf(r2 * 0.015625f - mu * mu + 1e-5f);
            hsow[d0] = (h0 - mu) * inv * g0 + lb0;
            hsow[d1] = (h1 - mu) * inv * g1 + lb1;
            im_cur = __expf(inv * (r3 - mu * Sgwi) + Sbwi + bi);
            float ef = __expf(-(inv * (r4 - mu * Sgwf) + Sbwf + bf));
            fm_cur = __fdividef(1.f, 1.f + ef);
        }
        __syncwarp();

        // ---- C(i-1): k/v projections (threads 0..127) ----
        if (t < 128) {
            ull a0 = 0, a1 = 0, a2 = 0, a3 = 0;
            const ulonglong2* h2 = reinterpret_cast<const ulonglong2*>(hsow);
#pragma unroll
            for (int q = 0; q < 8; q++) {
                ulonglong2 u = h2[2 * q];
                ulonglong2 v = h2[2 * q + 1];
                ffma2(a0, u.x, W2[4 * q]);
                ffma2(a1, u.y, W2[4 * q + 1]);
                ffma2(a2, v.x, W2[4 * q + 2]);
                ffma2(a3, v.y, W2[4 * q + 3]);
            }
            a0 = addf2(a0, a1); a2 = addf2(a2, a3); a0 = addf2(a0, a2);
            float2 p = unpackf2(a0);
            float acc = p.x + p.y;
            int buf = (i - 1) & 1;
            if (t < 64) kbuf[buf][t] = acc * 0.125f;
            else        vbuf[buf][t - 64] = acc;
        }

        // ---- D(i-2): C_m rank-1 update + n_m ----
        if (i >= 2) {
            int buf = i & 1;           // == (i-2)&1
            float imv = im_prev * vbuf[buf][ci];
            ull fm2 = packf2(fm_prev, fm_prev);
            ull iv2 = packf2(imv, imv);
            const ulonglong2* k2 = reinterpret_cast<const ulonglong2*>(&kbuf[buf][jb]);
#pragma unroll
            for (int q = 0; q < 4; q++) {
                ulonglong2 kv = k2[q];
                C2[2 * q]     = fmaf2(C2[2 * q],     fm2, mulf2(kv.x, iv2));
                C2[2 * q + 1] = fmaf2(C2[2 * q + 1], fm2, mulf2(kv.y, iv2));
            }
            if (t < 64) nm[t] = fm_prev * nm[t] + im_prev * kbuf[buf][t];
        }
        im_prev = im_cur; fm_prev = fm_cur;
        __syncthreads();
    }

    // ---- tail: B(511), C(511), D(510), D(511) ----
    {
        const float* gA = gact2[(S_DIM - 1) & 1];   // gact(511)
        float z0 = gA[d0], i0v = gA[64 + d0], f0 = gA[128 + d0], o0 = gA[192 + d0];
        float z1 = gA[d1], i1v = gA[64 + d1], f1 = gA[128 + d1], o1 = gA[192 + d1];
        cs0 = f0 * cs0 + i0v * z0; ns0 = f0 * ns0 + i0v;
        cs1 = f1 * cs1 + i1v * z1; ns1 = f1 * ns1 + i1v;
        float h0 = __fdividef(o0 * cs0, ns0);
        float h1 = __fdividef(o1 * cs1, ns1);

        float im_cur, fm_cur;
        {
            float r1 = h0 + h1;
            float r2 = h0 * h0 + h1 * h1;
            float r3 = h0 * gwi0 + h1 * gwi1;
            float r4 = h0 * gwf0 + h1 * gwf1;
#pragma unroll
            for (int off = 16; off > 0; off >>= 1) {
                r1 += __shfl_xor_sync(0xffffffffu, r1, off);
                r2 += __shfl_xor_sync(0xffffffffu, r2, off);
                r3 += __shfl_xor_sync(0xffffffffu, r3, off);
                r4 += __shfl_xor_sync(0xffffffffu, r4, off);
            }
            float mu  = r1 * 0.015625f;
            float inv = rsqrtf(r2 * 0.015625f - mu * mu + 1e-5f);
            hsow[d0] = (h0 - mu) * inv * g0 + lb0;
            hsow[d1] = (h1 - mu) * inv * g1 + lb1;
            im_cur = __expf(inv * (r3 - mu * Sgwi) + Sbwi + bi);
            float ef = __expf(-(inv * (r4 - mu * Sgwf) + Sbwf + bf));
            fm_cur = __fdividef(1.f, 1.f + ef);
        }
        __syncwarp();

        if (t < 128) {      // C(511) -> buffer (511)&1 = 1
            ull a0 = 0, a1 = 0, a2 = 0, a3 = 0;
            const ulonglong2* h2 = reinterpret_cast<const ulonglong2*>(hsow);
#pragma unroll
            for (int q = 0; q < 8; q++) {
                ulonglong2 u = h2[2 * q];
                ulonglong2 v = h2[2 * q + 1];
                ffma2(a0, u.x, W2[4 * q]);
                ffma2(a1, u.y, W2[4 * q + 1]);
                ffma2(a2, v.x, W2[4 * q + 2]);
                ffma2(a3, v.y, W2[4 * q + 3]);
            }
            a0 = addf2(a0, a1); a2 = addf2(a2, a3); a0 = addf2(a0, a2);
            float2 p = unpackf2(a0);
            float acc = p.x + p.y;
            if (t < 64) kbuf[1][t] = acc * 0.125f;
            else        vbuf[1][t - 64] = acc;
        }

        // D(510): buffer (510)&1 = 0, gates im/fm(510) = im_prev
        {
            float imv = im_prev * vbuf[0][ci];
            ull fm2 = packf2(fm_prev, fm_prev);
            ull iv2 = packf2(imv, imv);
            const ulonglong2* k2 = reinterpret_cast<const ulonglong2*>(&kbuf[0][jb]);
#pragma unroll
            for (int q = 0; q < 4; q++) {
                ulonglong2 kv = k2[q];
                C2[2 * q]     = fmaf2(C2[2 * q],     fm2, mulf2(kv.x, iv2));
                C2[2 * q + 1] = fmaf2(C2[2 * q + 1], fm2, mulf2(kv.y, iv2));
            }
            if (t < 64) nm[t] = fm_prev * nm[t] + im_prev * kbuf[0][t];
        }
        im_prev = im_cur; fm_prev = fm_cur;
        __syncthreads();

        // D(511): buffer 1, gates im/fm(511)
        {
            float imv = im_prev * vbuf[1][ci];
            ull fm2 = packf2(fm_prev, fm_prev);
            ull iv2 = packf2(imv, imv);
            const ulonglong2* k2 = reinterpret_cast<const ulonglong2*>(&kbuf[1][jb]);
#pragma unroll
            for (int q = 0; q < 4; q++) {
                ulonglong2 kv = k2[q];
                C2[2 * q]     = fmaf2(C2[2 * q],     fm2, mulf2(kv.x, iv2));
                C2[2 * q + 1] = fmaf2(C2[2 * q + 1], fm2, mulf2(kv.y, iv2));
            }
            if (t < 64) nm[t] = fm_prev * nm[t] + im_prev * kbuf[1][t];
        }
    }

    // ---- epilogue: q, om, num, den, h_m, fusion gate (uses hso(511)) ----
    float Creg[16];
#pragma unroll
    for (int i = 0; i < 8; i++) {
        float2 f = unpackf2(C2[i]);
        Creg[2 * i] = f.x; Creg[2 * i + 1] = f.y;
    }
    if (t < 128) {
        int c = t & 63;
        const float* W = (t < 64) ? Wq : Wo;
        float acc = (t < 64) ? 0.f : bo[c];
#pragma unroll
        for (int d = 0; d < 64; d++) acc += hsow[d] * W[d * 64 + c];
        if (t < 64) qsm[c] = acc;
        else        omsm[c] = 1.f / (1.f + expf(-acc));
    }
    __syncthreads();
    {
        float np = 0.f;
        const float4* q4p = reinterpret_cast<const float4*>(qsm + jb);
#pragma unroll
        for (int q4 = 0; q4 < 4; q4++) {
            float4 qq = q4p[q4];
            np += Creg[q4*4+0] * qq.x + Creg[q4*4+1] * qq.y
                + Creg[q4*4+2] * qq.z + Creg[q4*4+3] * qq.w;
        }
        np += __shfl_xor_sync(0xffffffffu, np, 1);
        np += __shfl_xor_sync(0xffffffffu, np, 2);
        if ((t & 3) == 0) numsm[ci] = np;
    }
    if (t < 64) {
        float dp = nm[t] * qsm[t];
#pragma unroll
        for (int off = 16; off > 0; off >>= 1)
            dp += __shfl_xor_sync(0xffffffffu, dp, off);
        if (lane == 0) red2[t >> 5] = dp;
    }
    __syncthreads();
    if (t < 64) {
        float den = fmaxf(fabsf(red2[0] + red2[1]), 1.f);
        hmsm[t] = omsm[t] * numsm[t] / den;
    }
    __syncthreads();
    {
        int j = t & 63, rb2 = (t >> 6) * 32;
        float gp = 0.f;
#pragma unroll
        for (int r = 0; r < 32; r++) {
            int rr = rb2 + r;
            float catv = (rr < 64) ? hsow[rr] : hmsm[rr - 64];
            gp += catv * W_fuse[rr * 64 + j];
        }
        gpart[t >> 6][j] = gp;
    }
    __syncthreads();
    if (t < 64) {
        float gs = gpart[0][t] + gpart[1][t] + gpart[2][t] + gpart[3][t] + b_fuse[t];
        float gate = 1.f / (1.f + expf(-gs));
        out[b * 64 + t] = gate * hmsm[t] + (1.f - gate) * hsow[t];
    }
}

// ---------------------------------------------------------------------------
extern "C" void kernel_launch(void* const* d_in, const int* in_sizes, int n_in,
                              void* d_out, int out_size) {
    const float* x      = (const float*)d_in[0];
    const float* W_in   = (const float*)d_in[1];
    const float* b_in   = (const float*)d_in[2];
    const float* W_s    = (const float*)d_in[3];
    const float* R_s    = (const float*)d_in[4];
    const float* b_s    = (const float*)d_in[5];
    const float* ln_g   = (const float*)d_in[6];
    const float* ln_b   = (const float*)d_in[7];
    const float* Wq     = (const float*)d_in[8];
    const float* Wk     = (const float*)d_in[9];
    const float* Wv     = (const float*)d_in[10];
    const float* wi     = (const float*)d_in[11];
    const float* bi     = (const float*)d_in[12];
    const float* wf     = (const float*)d_in[13];
    const float* bf     = (const float*)d_in[14];
    const float* Wo     = (const float*)d_in[15];
    const float* bo     = (const float*)d_in[16];
    const float* W_fuse = (const float*)d_in[17];
    const float* b_fuse = (const float*)d_in[18];
    float* out = (float*)d_out;

    combine_weights<<<IN_DIM + 1, G_DIM>>>(W_in, b_in, W_s, b_s);
    xs_gemm<<<(B_DIM * S_DIM) / TILE_R, 256>>>(x);
    recur<<<B_DIM, 256>>>(R_s, ln_g, ln_b, Wq, Wk, Wv, wi, bi, wf, bf,
                          Wo, bo, W_fuse, b_fuse, out);
}

// round 6
// speedup vs baseline: 1.0388x; 1.0388x over previous
#include <cuda_runtime.h>
#include <math.h>

#define B_DIM 128
#define S_DIM 512
#define IN_DIM 128
#define D_DIM 64
#define G_DIM 256   // 4*D
#define TILE_R 64

typedef unsigned long long ull;

// ---- packed f32x2 helpers (Blackwell; ptxas never auto-fuses these) ----
__device__ __forceinline__ void ffma2(ull& a, ull x, ull y) {
    asm("fma.rn.f32x2 %0, %1, %2, %0;" : "+l"(a) : "l"(x), "l"(y));
}
__device__ __forceinline__ ull fmaf2(ull a, ull b, ull c) {
    ull d; asm("fma.rn.f32x2 %0, %1, %2, %3;" : "=l"(d) : "l"(a), "l"(b), "l"(c)); return d;
}
__device__ __forceinline__ ull mulf2(ull x, ull y) {
    ull r; asm("mul.rn.f32x2 %0, %1, %2;" : "=l"(r) : "l"(x), "l"(y)); return r;
}
__device__ __forceinline__ ull addf2(ull x, ull y) {
    ull r; asm("add.rn.f32x2 %0, %1, %2;" : "=l"(r) : "l"(x), "l"(y)); return r;
}
__device__ __forceinline__ ull packf2(float lo, float hi) {
    ull r; asm("mov.b64 %0, {%1, %2};" : "=l"(r) : "f"(lo), "f"(hi)); return r;
}
__device__ __forceinline__ float2 unpackf2(ull v) {
    float2 f; asm("mov.b64 {%0, %1}, %2;" : "=f"(f.x), "=f"(f.y) : "l"(v)); return f;
}
// named CTA barrier, 512 threads, callable from divergent (warp-aligned) branches
#define BARX(id) asm volatile("bar.sync %0, %1;" :: "r"(id), "r"(512) : "memory")

// Scratch (sanctioned __device__ globals)
__device__ float g_xs[(size_t)S_DIM * B_DIM * G_DIM];   // [s][b][4D]
__device__ float g_Wc[IN_DIM * G_DIM];                  // W_in @ W_s
__device__ float g_bc[G_DIM];                           // b_in @ W_s + b_s

// ---------------------------------------------------------------------------
// Kernel 1: fold input projection into sLSTM input weights.
// ---------------------------------------------------------------------------
__global__ void combine_weights(const float* __restrict__ W_in,
                                const float* __restrict__ b_in,
                                const float* __restrict__ W_s,
                                const float* __restrict__ b_s) {
    int j = threadIdx.x;
    int d = blockIdx.x;
    if (d < IN_DIM) {
        float acc = 0.f;
#pragma unroll
        for (int e = 0; e < D_DIM; e++)
            acc += W_in[d * D_DIM + e] * W_s[e * G_DIM + j];
        g_Wc[d * G_DIM + j] = acc;
    } else {
        float acc = b_s[j];
#pragma unroll
        for (int e = 0; e < D_DIM; e++)
            acc += b_in[e] * W_s[e * G_DIM + j];
        g_bc[j] = acc;
    }
}

// ---------------------------------------------------------------------------
// Kernel 2: xs[s][b][j] = x[b][s][:] @ W_comb[:,j] + b_comb[j]  (packed f32x2)
// ---------------------------------------------------------------------------
__global__ __launch_bounds__(256) void xs_gemm(const float* __restrict__ x) {
    __shared__ __align__(16) float xsm[TILE_R][IN_DIM];
    int t = threadIdx.x;
    int row0 = blockIdx.x * TILE_R;

    const float4* xg = reinterpret_cast<const float4*>(x + (size_t)row0 * IN_DIM);
    float4* xs4 = reinterpret_cast<float4*>(&xsm[0][0]);
#pragma unroll
    for (int i = 0; i < (TILE_R * IN_DIM / 4) / 256; i++)
        xs4[t + i * 256] = xg[t + i * 256];

    ull w2[64];
#pragma unroll
    for (int i = 0; i < 64; i++)
        w2[i] = packf2(g_Wc[(2 * i) * G_DIM + t], g_Wc[(2 * i + 1) * G_DIM + t]);
    float bc = g_bc[t];
    __syncthreads();

    for (int r = 0; r < TILE_R; r += 4) {
        ull a0 = 0, a1 = 0, a2 = 0, a3 = 0;
        const ulonglong2* p0 = reinterpret_cast<const ulonglong2*>(xsm[r + 0]);
        const ulonglong2* p1 = reinterpret_cast<const ulonglong2*>(xsm[r + 1]);
        const ulonglong2* p2 = reinterpret_cast<const ulonglong2*>(xsm[r + 2]);
        const ulonglong2* p3 = reinterpret_cast<const ulonglong2*>(xsm[r + 3]);
#pragma unroll
        for (int dq = 0; dq < 32; dq++) {
            ulonglong2 v0 = p0[dq]; ffma2(a0, v0.x, w2[2*dq]); ffma2(a0, v0.y, w2[2*dq+1]);
            ulonglong2 v1 = p1[dq]; ffma2(a1, v1.x, w2[2*dq]); ffma2(a1, v1.y, w2[2*dq+1]);
            ulonglong2 v2 = p2[dq]; ffma2(a2, v2.x, w2[2*dq]); ffma2(a2, v2.y, w2[2*dq+1]);
            ulonglong2 v3 = p3[dq]; ffma2(a3, v3.x, w2[2*dq]); ffma2(a3, v3.y, w2[2*dq+1]);
        }
#pragma unroll
        for (int rr = 0; rr < 4; rr++) {
            ull av = (rr == 0) ? a0 : (rr == 1) ? a1 : (rr == 2) ? a2 : a3;
            float2 f = unpackf2(av);
            int row = row0 + r + rr;
            int bb = row >> 9;
            int ss = row & 511;
            g_xs[((size_t)ss * B_DIM + bb) * G_DIM + t] = f.x + f.y + bc;
        }
    }
}

// ---------------------------------------------------------------------------
// Kernel 3: warp-specialized recurrence. 512 threads/CTA, 1 CTA/batch.
//   GATE  (t   0..255): A = gate matvec+activation; warp 0 also runs B
//                       (state, LN, scalar gates). Holds R2 in regs.
//   KV    (t 256..383): C = k/v projections. Holds W2 in regs.
//   MEM   (t 384..511): D = C_m rank-1 update + n_m; final num. Holds C2.
// Disjoint top-level branches -> ptxas overlays R2/W2/C2.
// Schedule per it: B(it-1) ; BAR1 ; { A(it) || C(it-1) || D(it-2) } ; BAR2.
// ---------------------------------------------------------------------------
__global__ __launch_bounds__(512, 1) void recur(
    const float* __restrict__ R_s,
    const float* __restrict__ ln_g, const float* __restrict__ ln_b,
    const float* __restrict__ Wq, const float* __restrict__ Wk,
    const float* __restrict__ Wv,
    const float* __restrict__ wi, const float* __restrict__ bi_p,
    const float* __restrict__ wf, const float* __restrict__ bf_p,
    const float* __restrict__ Wo, const float* __restrict__ bo,
    const float* __restrict__ W_fuse, const float* __restrict__ b_fuse,
    float* __restrict__ out)
{
    __shared__ __align__(16) float hs[64], hso[64], gact[256], nm[64];
    __shared__ __align__(16) float kbuf[2][64], vbuf[2][64];
    __shared__ float scl[2][2];                        // [parity][im,fm]
    __shared__ __align__(16) float qsm[64], omsm[64], numsm[64], hmsm[64];
    __shared__ float red2[2];
    __shared__ float gpart[4][64];

    const int t = threadIdx.x;
    const int b = blockIdx.x;
    const int lane = t & 31;

    if (t < 64) { hs[t] = 0.f; nm[t] = 0.f; }
    __syncthreads();

    if (t < 256) {
        // ================= GATE group =================
        ull R2[32];
#pragma unroll
        for (int i = 0; i < 32; i++)
            R2[i] = packf2(R_s[(2 * i) * G_DIM + t], R_s[(2 * i + 1) * G_DIM + t]);

        // warp-0 B constants
        float cs0 = 0.f, cs1 = 0.f, ns0 = 1.f, ns1 = 1.f;
        float g0 = 0.f, g1 = 0.f, lb0 = 0.f, lb1 = 0.f;
        float gwi0 = 0.f, gwi1 = 0.f, gwf0 = 0.f, gwf1 = 0.f;
        float Sgwi = 0.f, Sgwf = 0.f, Sbwi = 0.f, Sbwf = 0.f;
        float bi = 0.f, bf = 0.f;
        const int d0 = lane, d1 = lane + 32;
        if (t < 32) {
            g0 = ln_g[d0]; g1 = ln_g[d1]; lb0 = ln_b[d0]; lb1 = ln_b[d1];
            float wi0 = wi[d0], wi1 = wi[d1], wf0 = wf[d0], wf1 = wf[d1];
            gwi0 = g0 * wi0; gwi1 = g1 * wi1; gwf0 = g0 * wf0; gwf1 = g1 * wf1;
            float sa = gwi0 + gwi1, sb = gwf0 + gwf1;
            float sc = lb0 * wi0 + lb1 * wi1, sd = lb0 * wf0 + lb1 * wf1;
#pragma unroll
            for (int off = 16; off > 0; off >>= 1) {
                sa += __shfl_xor_sync(0xffffffffu, sa, off);
                sb += __shfl_xor_sync(0xffffffffu, sb, off);
                sc += __shfl_xor_sync(0xffffffffu, sc, off);
                sd += __shfl_xor_sync(0xffffffffu, sd, off);
            }
            Sgwi = sa; Sgwf = sb; Sbwi = sc; Sbwf = sd;
            bi = bi_p[0]; bf = bf_p[0];
        }

        const float* xsp = g_xs + (size_t)b * G_DIM + t;
        float gnext = xsp[0];

        for (int it = 0; it <= 514; it++) {
            // ---- B(it-1), warp 0 only ----
            if (t < 32 && it >= 1 && it <= 512) {
                float z0 = gact[d0], i0v = gact[64 + d0], f0 = gact[128 + d0], o0 = gact[192 + d0];
                float z1 = gact[d1], i1v = gact[64 + d1], f1 = gact[128 + d1], o1 = gact[192 + d1];
                cs0 = f0 * cs0 + i0v * z0; ns0 = f0 * ns0 + i0v;
                cs1 = f1 * cs1 + i1v * z1; ns1 = f1 * ns1 + i1v;
                float h0 = __fdividef(o0 * cs0, ns0);
                float h1 = __fdividef(o1 * cs1, ns1);
                hs[d0] = h0; hs[d1] = h1;
                float r1 = h0 + h1;
                float r2 = h0 * h0 + h1 * h1;
                float r3 = h0 * gwi0 + h1 * gwi1;
                float r4 = h0 * gwf0 + h1 * gwf1;
#pragma unroll
                for (int off = 16; off > 0; off >>= 1) {
                    r1 += __shfl_xor_sync(0xffffffffu, r1, off);
                    r2 += __shfl_xor_sync(0xffffffffu, r2, off);
                    r3 += __shfl_xor_sync(0xffffffffu, r3, off);
                    r4 += __shfl_xor_sync(0xffffffffu, r4, off);
                }
                float mu  = r1 * 0.015625f;
                float inv = rsqrtf(r2 * 0.015625f - mu * mu + 1e-5f);
                hso[d0] = (h0 - mu) * inv * g0 + lb0;
                hso[d1] = (h1 - mu) * inv * g1 + lb1;
                if (lane == 0) {
                    int pb = (it - 1) & 1;
                    scl[pb][0] = __expf(inv * (r3 - mu * Sgwi) + Sbwi + bi);
                    float ef = __expf(-(inv * (r4 - mu * Sgwf) + Sbwf + bf));
                    scl[pb][1] = __fdividef(1.f, 1.f + ef);
                }
            }
            BARX(1);
            if (it <= 511) {
                // ---- A(it): g = xs(it) + hs(it-1) @ R_s ; activation ----
                float gv = gnext;
                {
                    int sn = (it + 1 < S_DIM) ? (it + 1) : (S_DIM - 1);
                    gnext = xsp[(size_t)sn * (B_DIM * G_DIM)];
                }
                ull a0 = 0, a1 = 0, a2 = 0, a3 = 0;
                const ulonglong2* h2 = reinterpret_cast<const ulonglong2*>(hs);
#pragma unroll
                for (int q = 0; q < 8; q++) {
                    ulonglong2 u = h2[2 * q];
                    ulonglong2 v = h2[2 * q + 1];
                    ffma2(a0, u.x, R2[4 * q]);
                    ffma2(a1, u.y, R2[4 * q + 1]);
                    ffma2(a2, v.x, R2[4 * q + 2]);
                    ffma2(a3, v.y, R2[4 * q + 3]);
                }
                a0 = addf2(a0, a1); a2 = addf2(a2, a3); a0 = addf2(a0, a2);
                float2 p = unpackf2(a0);
                gv += p.x + p.y;
                float act;
                if (t < 64)       { float e = __expf(2.f * gv); act = 1.f - __fdividef(2.f, e + 1.f); }
                else if (t < 128) { act = __expf(gv); }
                else              { float e = __expf(-gv); act = __fdividef(1.f, 1.f + e); }
                gact[t] = act;
            } else if (it == 513 && t < 128) {
                // ---- q / om projections on hso(511) ----
                int c = t & 63;
                const float* W = (t < 64) ? Wq : Wo;
                float acc = (t < 64) ? 0.f : bo[c];
#pragma unroll
                for (int d = 0; d < 64; d++) acc += hso[d] * W[d * 64 + c];
                if (t < 64) qsm[c] = acc;
                else        omsm[c] = 1.f / (1.f + expf(-acc));
            }
            BARX(2);
        }
    } else if (t < 384) {
        // ================= KV group =================
        const int tk = t - 256;
        const float* Wsel = (tk < 64) ? Wk : Wv;
        const int c = tk & 63;
        ull W2[32];
#pragma unroll
        for (int i = 0; i < 32; i++)
            W2[i] = packf2(Wsel[(2 * i) * 64 + c], Wsel[(2 * i + 1) * 64 + c]);

        for (int it = 0; it <= 514; it++) {
            BARX(1);
            if (it >= 1 && it <= 512) {
                // ---- C(it-1): k = hso@Wk * d^-1/2 ; v = hso@Wv ----
                ull a0 = 0, a1 = 0, a2 = 0, a3 = 0;
                const ulonglong2* h2 = reinterpret_cast<const ulonglong2*>(hso);
#pragma unroll
                for (int q = 0; q < 8; q++) {
                    ulonglong2 u = h2[2 * q];
                    ulonglong2 v = h2[2 * q + 1];
                    ffma2(a0, u.x, W2[4 * q]);
                    ffma2(a1, u.y, W2[4 * q + 1]);
                    ffma2(a2, v.x, W2[4 * q + 2]);
                    ffma2(a3, v.y, W2[4 * q + 3]);
                }
                a0 = addf2(a0, a1); a2 = addf2(a2, a3); a0 = addf2(a0, a2);
                float2 p = unpackf2(a0);
                float acc = p.x + p.y;
                int buf = (it - 1) & 1;
                if (tk < 64) kbuf[buf][tk] = acc * 0.125f;
                else         vbuf[buf][tk - 64] = acc;
            }
            BARX(2);
        }
    } else {
        // ================= MEM group =================
        const int tm = t - 384;            // 0..127
        const int row = tm >> 1;           // C_m row (2 threads/row)
        const int half = (tm & 1) << 5;    // 32-column slice
        ull C2[16];
#pragma unroll
        for (int i = 0; i < 16; i++) C2[i] = 0ull;

        for (int it = 0; it <= 514; it++) {
            BARX(1);
            if (it >= 2 && it <= 513) {
                // ---- D(it-2): C_m = fm*C_m + im * v k^T ; n_m update ----
                int buf = it & 1;          // == (it-2)&1
                float im = scl[buf][0], fm = scl[buf][1];
                float imv = im * vbuf[buf][row];
                ull fm2 = packf2(fm, fm);
                ull iv2 = packf2(imv, imv);
                const ulonglong2* k2 = reinterpret_cast<const ulonglong2*>(&kbuf[buf][half]);
#pragma unroll
                for (int q = 0; q < 8; q++) {
                    ulonglong2 kv = k2[q];
                    C2[2 * q]     = fmaf2(C2[2 * q],     fm2, mulf2(kv.x, iv2));
                    C2[2 * q + 1] = fmaf2(C2[2 * q + 1], fm2, mulf2(kv.y, iv2));
                }
                if (tm < 64) nm[tm] = fm * nm[tm] + im * kbuf[buf][tm];
            } else if (it == 514) {
                // ---- num[row] = C_m[row,:] . q ----
                float np = 0.f;
                const float4* q4p = reinterpret_cast<const float4*>(qsm + half);
#pragma unroll
                for (int q = 0; q < 8; q++) {
                    float4 qq = q4p[q];
                    float2 c0 = unpackf2(C2[2 * q]);
                    float2 c1 = unpackf2(C2[2 * q + 1]);
                    np += c0.x * qq.x + c0.y * qq.y + c1.x * qq.z + c1.y * qq.w;
                }
                np += __shfl_xor_sync(0xffffffffu, np, 1);
                if ((tm & 1) == 0) numsm[row] = np;
            }
            BARX(2);
        }
    }

    // ---- reconverged epilogue ----
    __syncthreads();
    if (t < 64) {
        float dp = nm[t] * qsm[t];
#pragma unroll
        for (int off = 16; off > 0; off >>= 1)
            dp += __shfl_xor_sync(0xffffffffu, dp, off);
        if (lane == 0) red2[t >> 5] = dp;
    }
    __syncthreads();
    if (t < 64) {
        float den = fmaxf(fabsf(red2[0] + red2[1]), 1.f);
        hmsm[t] = omsm[t] * numsm[t] / den;
    }
    __syncthreads();
    if (t < 256) {
        int j = t & 63, rb2 = (t >> 6) * 32;
        float gp = 0.f;
#pragma unroll
        for (int r = 0; r < 32; r++) {
            int rr = rb2 + r;
            float catv = (rr < 64) ? hso[rr] : hmsm[rr - 64];
            gp += catv * W_fuse[rr * 64 + j];
        }
        gpart[t >> 6][j] = gp;
    }
    __syncthreads();
    if (t < 64) {
        float gs = gpart[0][t] + gpart[1][t] + gpart[2][t] + gpart[3][t] + b_fuse[t];
        float gate = 1.f / (1.f + expf(-gs));
        out[b * 64 + t] = gate * hmsm[t] + (1.f - gate) * hso[t];
    }
}

// ---------------------------------------------------------------------------
extern "C" void kernel_launch(void* const* d_in, const int* in_sizes, int n_in,
                              void* d_out, int out_size) {
    const float* x      = (const float*)d_in[0];
    const float* W_in   = (const float*)d_in[1];
    const float* b_in   = (const float*)d_in[2];
    const float* W_s    = (const float*)d_in[3];
    const float* R_s    = (const float*)d_in[4];
    const float* b_s    = (const float*)d_in[5];
    const float* ln_g   = (const float*)d_in[6];
    const float* ln_b   = (const float*)d_in[7];
    const float* Wq     = (const float*)d_in[8];
    const float* Wk     = (const float*)d_in[9];
    const float* Wv     = (const float*)d_in[10];
    const float* wi     = (const float*)d_in[11];
    const float* bi     = (const float*)d_in[12];
    const float* wf     = (const float*)d_in[13];
    const float* bf     = (const float*)d_in[14];
    const float* Wo     = (const float*)d_in[15];
    const float* bo     = (const float*)d_in[16];
    const float* W_fuse = (const float*)d_in[17];
    const float* b_fuse = (const float*)d_in[18];
    float* out = (float*)d_out;

    combine_weights<<<IN_DIM + 1, G_DIM>>>(W_in, b_in, W_s, b_s);
    xs_gemm<<<(B_DIM * S_DIM) / TILE_R, 256>>>(x);
    recur<<<B_DIM, 512>>>(R_s, ln_g, ln_b, Wq, Wk, Wv, wi, bi, wf, bf,
                          Wo, bo, W_fuse, b_fuse, out);
}